// round 12
// baseline (speedup 1.0000x reference)
#include <cuda_runtime.h>
#include <cstdint>

#define BB 32
#define CC 128
#define HH 56
#define WW 56

// ---------------- scratch (module-static device memory; no allocs) ----------------
__device__ uint8_t g_ah[BB * HH * WW * CC];   // u8 high acts, NHWC (128 B/pixel)
__device__ uint8_t g_al[BB * HH * WW * CC];   // u8 low  acts, NHWC (128 B/pixel)
__device__ int8_t  g_whP[9 * CC * CC];        // s8 high weights [k][co][32 packed words]
__device__ int8_t  g_wlT[9 * 2 * 32 * 64 * 4];// s8 low weights [k][ch][ci4][wn][j2][t][4w]
__device__ float   g_fsh[CC];                 // fused scale high
__device__ float   g_fsl[CC];                 // fused scale low

__device__ __forceinline__ int dp4a_us(unsigned a, unsigned b, int c) {
    int r;
    asm("dp4a.u32.s32 %0, %1, %2, %3;" : "=r"(r) : "r"(a), "r"(b), "r"(c));
    return r;
}

// ---------------- K1: per-output-channel weight quantization ----------------
__global__ __launch_bounds__(256) void quant_weights_kernel(
    const float* __restrict__ w, const float* __restrict__ as_ptr,
    float nlev, int which)
{
    int co = blockIdx.x;
    int tid = threadIdx.x;
    const float* wc = w + co * (CC * 9);

    float mx = 0.f;
    for (int i = tid; i < CC * 9; i += 256) mx = fmaxf(mx, fabsf(wc[i]));
    __shared__ float red[256];
    red[tid] = mx;
    __syncthreads();
    for (int s = 128; s > 0; s >>= 1) {
        if (tid < s) red[tid] = fmaxf(red[tid], red[tid + s]);
        __syncthreads();
    }
    float s = red[0] / nlev;

    // decompositions for packed layouts
    int ch = co >> 6;
    int wn = (co >> 5) & 1;
    int r5 = co & 31;
    int ntc = r5 >> 3, tt = (r5 >> 1) & 3, wb = r5 & 1;
    int w8 = ntc * 2 + wb, j2 = w8 >> 2, wq4 = w8 & 3;

    for (int i = tid; i < CC * 9; i += 256) {
        float q = rintf(wc[i] / s);
        q = fminf(fmaxf(q, -nlev), nlev);
        int ci = i / 9, k = i % 9;                 // OIHW: i = ci*9 + k
        if (which == 0) {
            // mma B-fragment packed layout:
            // chunk = ci>>5, j = (ci&31)>>4, t4 = (ci>>2)&3, byte = ci&3
            int chunk = ci >> 5;
            int j = (ci & 31) >> 4;
            int t4 = (ci >> 2) & 3;
            int P = (chunk < 2) ? (t4 * 4 + chunk * 2 + j)
                                : (16 + t4 * 4 + (chunk - 2) * 2 + j);
            g_whP[((k * CC + co) * 32 + P) * 4 + (ci & 3)] = (int8_t)q;
        } else {
            int ci4 = ci >> 2;
            int word = ((k * 2 + ch) * 32 + ci4) * 64
                     + wn * 32 + j2 * 16 + tt * 4 + wq4;
            g_wlT[word * 4 + (ci & 3)] = (int8_t)q;
        }
    }
    if (tid == 0) {
        if (which) g_fsl[co] = s * as_ptr[0];
        else       g_fsh[co] = s * as_ptr[0];
    }
}

// ---------------- K2: predictor mask + activation fake-quant -> NHWC uint8 ----------------
__global__ __launch_bounds__(256) void mask_quant_kernel(
    const float* __restrict__ x,
    const float* __restrict__ ash_p, const float* __restrict__ asl_p)
{
    int bw = blockIdx.x, bh = blockIdx.y, b = blockIdx.z;
    int tid = threadIdx.x;
    int h0 = bh * 8, w0 = bw * 8;

    __shared__ float sx[64][CC + 1];
    __shared__ uint8_t smask[CC];

    for (int i = tid; i < 64 * CC; i += 256) {
        int c = i >> 6, p = i & 63;
        sx[p][c] = x[((b * CC + c) * HH + h0 + (p >> 3)) * WW + w0 + (p & 7)];
    }
    __syncthreads();

    int lane = tid & 31, wrp = tid >> 5;
    for (int j = 0; j < 16; j++) {
        int c = wrp * 16 + j;
        float v = sx[lane][c] + sx[lane + 32][c];
        #pragma unroll
        for (int o = 16; o > 0; o >>= 1) v += __shfl_xor_sync(0xffffffffu, v, o);
        if (lane == 0) smask[c] = (v * (1.0f / 64.0f) >= 0.05f) ? 1 : 0;
    }
    __syncthreads();

    float ash = ash_p[0], asl = asl_p[0];
    for (int i = tid; i < 64 * (CC / 4); i += 256) {
        int p = i >> 5, c4 = (i & 31);
        int hh = h0 + (p >> 3), ww = w0 + (p & 7);
        unsigned qh = 0u, ql = 0u;
        #pragma unroll
        for (int j = 0; j < 4; j++) {
            int c = c4 * 4 + j;
            float v = sx[p][c];
            bool m = smask[c] != 0;
            float fh = fminf(fmaxf(rintf(v / ash), 0.f), 255.f);
            float fl = fminf(fmaxf(rintf(v / asl), 0.f), 15.f);
            unsigned b8h = m ? (unsigned)fh : 0u;
            unsigned b8l = m ? 0u : (unsigned)fl;
            qh |= b8h << (8 * j);
            ql |= b8l << (8 * j);
        }
        int base = ((b * HH + hh) * WW + ww) * (CC / 4) + c4;
        ((unsigned*)g_ah)[base] = qh;
        ((unsigned*)g_al)[base] = ql;
    }
}

// ---------------- K3: hybrid conv3x3 — weights via LDG, acts via smem ----------------
// CTA: 256 thr, 8 warps (4M x 2N), tile 64 pix x 64 co, 3 CTAs/SM.
// No weight staging, no mainloop barriers. mma B-fragments and dp4a weights
// come straight from packed global layouts (L1D/L2-resident, sector-dense).

#define ROWB 144
#define ACT_H_OFF 0
#define ACT_L_OFF 14400                         // 100*144
#define CONV_SMEM 28800                         // act tiles only

__device__ __forceinline__ void mma_u8s8(int* c, const unsigned* a, unsigned b0, unsigned b1) {
    asm volatile(
        "mma.sync.aligned.m16n8k32.row.col.s32.u8.s8.s32 "
        "{%0,%1,%2,%3}, {%4,%5,%6,%7}, {%8,%9}, {%0,%1,%2,%3};"
        : "+r"(c[0]), "+r"(c[1]), "+r"(c[2]), "+r"(c[3])
        : "r"(a[0]), "r"(a[1]), "r"(a[2]), "r"(a[3]), "r"(b0), "r"(b1));
}

__device__ __forceinline__ void ldsm_x4(unsigned addr, unsigned* r) {
    asm volatile(
        "ldmatrix.sync.aligned.m8n8.x4.shared.b16 {%0,%1,%2,%3}, [%4];"
        : "=r"(r[0]), "=r"(r[1]), "=r"(r[2]), "=r"(r[3]) : "r"(addr));
}

__global__ __launch_bounds__(256, 3) void conv_hybrid_kernel(float* __restrict__ out)
{
    extern __shared__ __align__(16) char smem[];
    unsigned sb32 = (unsigned)__cvta_generic_to_shared(smem);

    int tid = threadIdx.x;
    int bz = blockIdx.z;
    int b = bz >> 1;
    int co0 = (bz & 1) * 64;
    int ch = co0 >> 6;
    int h0 = blockIdx.y * 8, w0 = blockIdx.x * 8;

    // act halo tiles (both convs): 1600 16B chunks; invalid -> zero store
    #pragma unroll
    for (int j = 0; j < 7; j++) {
        int i = tid + j * 256;
        if (i < 1600) {
            int cv = i / 800, r = i % 800;
            int p = r >> 3, c16 = r & 7;
            int pr = p / 10 - 1 + h0, pc = p % 10 - 1 + w0;
            char* dgen = smem + (cv ? ACT_L_OFF : ACT_H_OFF) + p * ROWB + c16 * 16;
            if (pr >= 0 && pr < HH && pc >= 0 && pc < WW) {
                const char* src = (const char*)(cv ? g_al : g_ah)
                                  + ((size_t)((b * HH + pr) * WW + pc)) * 128 + c16 * 16;
                unsigned d = (unsigned)__cvta_generic_to_shared(dgen);
                asm volatile("cp.async.cg.shared.global [%0], [%1], 16;" :: "r"(d), "l"(src));
            } else {
                *(uint4*)dgen = make_uint4(0u, 0u, 0u, 0u);
            }
        }
    }
    asm volatile("cp.async.commit_group;" ::: "memory");

    int lane = tid & 31, warp = tid >> 5;
    int wm = warp >> 1;          // 0..3 : 16-pixel group (rows 2wm, 2wm+1)
    int wn = warp & 1;           // 0..1 : 32-co group
    int g = lane >> 2, t = lane & 3;

    // ldmatrix lane roles (A operand)
    int lg = lane & 7;
    int rsel = (lane >> 3) & 1;
    int hi16 = (lane >> 4) & 1;

    int acch[4][4], accl[4][4];  // [nt][e]; e: 0,1 = row pin0 co,co+1; 2,3 = row pin1
    #pragma unroll
    for (int nt = 0; nt < 4; nt++)
        #pragma unroll
        for (int q = 0; q < 4; q++) { acch[nt][q] = 0; accl[nt][q] = 0; }

    const char* s_al = smem + ACT_L_OFF;

    asm volatile("cp.async.wait_group 0;" ::: "memory");
    __syncthreads();             // acts ready; mainloop is barrier-free

    #pragma unroll 1
    for (int k9 = 0; k9 < 9; k9++) {
        int kh = k9 / 3, kw = k9 - kh * 3;

        // ---- high conv: A via LDSM from smem, B via packed LDG ----
        unsigned aAddr = sb32 + ACT_H_OFF
                       + (unsigned)(((2 * wm + kh) * 10 + lg + kw + 10 * rsel) * ROWB)
                       + (unsigned)(hi16 * 16);
        unsigned a[4][4];
        #pragma unroll
        for (int chunk = 0; chunk < 4; chunk++)
            ldsm_x4(aAddr + chunk * 32, a[chunk]);

        #pragma unroll
        for (int nt = 0; nt < 4; nt++) {
            const uint4* wb = (const uint4*)(g_whP
                + ((size_t)(k9 * CC + co0 + wn * 32 + nt * 8 + g) << 7)) + t;
            uint4 v0 = wb[0];                    // chunks 0,1: {b0,b1,b0,b1}
            uint4 v1 = wb[4];                    // chunks 2,3
            mma_u8s8(acch[nt], a[0], v0.x, v0.y);
            mma_u8s8(acch[nt], a[1], v0.z, v0.w);
            mma_u8s8(acch[nt], a[2], v1.x, v1.y);
            mma_u8s8(acch[nt], a[3], v1.z, v1.w);
        }

        // ---- low conv: acts via LDS, weights via packed LDG (4 sectors/ci4) ----
        int pin0 = (2 * wm + kh) * 10 + g + kw;
        int pin1 = pin0 + 10;
        const char* wlk = (const char*)g_wlT
            + (size_t)((k9 * 2 + ch) * 32) * 256 + wn * 128 + t * 16;
        #pragma unroll
        for (int seg = 0; seg < 8; seg++) {
            uint4 a0 = *(const uint4*)(s_al + pin0 * ROWB + seg * 16);
            uint4 a1 = *(const uint4*)(s_al + pin1 * ROWB + seg * 16);
            const unsigned aw0[4] = {a0.x, a0.y, a0.z, a0.w};
            const unsigned aw1[4] = {a1.x, a1.y, a1.z, a1.w};
            #pragma unroll
            for (int q = 0; q < 4; q++) {
                const char* wp = wlk + (seg * 4 + q) * 256;
                uint4 wv0 = *(const uint4*)wp;          // w8 = 0..3
                uint4 wv1 = *(const uint4*)(wp + 64);   // w8 = 4..7
                accl[0][0] = dp4a_us(aw0[q], wv0.x, accl[0][0]);
                accl[0][1] = dp4a_us(aw0[q], wv0.y, accl[0][1]);
                accl[1][0] = dp4a_us(aw0[q], wv0.z, accl[1][0]);
                accl[1][1] = dp4a_us(aw0[q], wv0.w, accl[1][1]);
                accl[2][0] = dp4a_us(aw0[q], wv1.x, accl[2][0]);
                accl[2][1] = dp4a_us(aw0[q], wv1.y, accl[2][1]);
                accl[3][0] = dp4a_us(aw0[q], wv1.z, accl[3][0]);
                accl[3][1] = dp4a_us(aw0[q], wv1.w, accl[3][1]);
                accl[0][2] = dp4a_us(aw1[q], wv0.x, accl[0][2]);
                accl[0][3] = dp4a_us(aw1[q], wv0.y, accl[0][3]);
                accl[1][2] = dp4a_us(aw1[q], wv0.z, accl[1][2]);
                accl[1][3] = dp4a_us(aw1[q], wv0.w, accl[1][3]);
                accl[2][2] = dp4a_us(aw1[q], wv1.x, accl[2][2]);
                accl[2][3] = dp4a_us(aw1[q], wv1.y, accl[2][3]);
                accl[3][2] = dp4a_us(aw1[q], wv1.z, accl[3][2]);
                accl[3][3] = dp4a_us(aw1[q], wv1.w, accl[3][3]);
            }
        }
    }

    // epilogue: y = fsh*acc_h + fsl*acc_l -> NCHW fp32
    int p0 = wm * 16 + g;
    int oh0 = h0 + (p0 >> 3), ow = w0 + (p0 & 7);
    int oh1 = oh0 + 1;                               // pin1 row = next image row
    #pragma unroll
    for (int nt = 0; nt < 4; nt++) {
        int cg0 = co0 + wn * 32 + nt * 8 + t * 2;
        float sh0 = g_fsh[cg0],     sl0 = g_fsl[cg0];
        float sh1 = g_fsh[cg0 + 1], sl1 = g_fsl[cg0 + 1];
        out[((b * CC + cg0) * HH + oh0) * WW + ow] =
            sh0 * (float)acch[nt][0] + sl0 * (float)accl[nt][0];
        out[((b * CC + cg0 + 1) * HH + oh0) * WW + ow] =
            sh1 * (float)acch[nt][1] + sl1 * (float)accl[nt][1];
        out[((b * CC + cg0) * HH + oh1) * WW + ow] =
            sh0 * (float)acch[nt][2] + sl0 * (float)accl[nt][2];
        out[((b * CC + cg0 + 1) * HH + oh1) * WW + ow] =
            sh1 * (float)acch[nt][3] + sl1 * (float)accl[nt][3];
    }
}

// ---------------- launch ----------------
extern "C" void kernel_launch(void* const* d_in, const int* in_sizes, int n_in,
                              void* d_out, int out_size)
{
    const float* x      = (const float*)d_in[0];
    const float* w_high = (const float*)d_in[1];
    const float* w_low  = (const float*)d_in[2];
    const float* as_h   = (const float*)d_in[3];
    const float* as_l   = (const float*)d_in[4];
    float* out = (float*)d_out;

    cudaFuncSetAttribute(conv_hybrid_kernel,
                         cudaFuncAttributeMaxDynamicSharedMemorySize, CONV_SMEM);

    quant_weights_kernel<<<CC, 256>>>(w_high, as_h, 127.0f, 0);
    quant_weights_kernel<<<CC, 256>>>(w_low,  as_l,   7.0f, 1);
    mask_quant_kernel<<<dim3(WW / 8, HH / 8, BB), 256>>>(x, as_h, as_l);
    conv_hybrid_kernel<<<dim3(WW / 8, HH / 8, BB * 2), 256, CONV_SMEM>>>(out);
}

// round 13
// speedup vs baseline: 1.1723x; 1.1723x over previous
#include <cuda_runtime.h>
#include <cstdint>

#define BB 32
#define CC 128
#define HH 56
#define WW 56

// ---------------- scratch (module-static device memory; no allocs) ----------------
__device__ uint8_t g_ah[BB * HH * WW * CC];   // u8 high acts, NHWC (128 B/pixel)
__device__ uint8_t g_al[BB * HH * WW * CC];   // u8 low  acts, NHWC (128 B/pixel)
__device__ int8_t  g_wh[CC * 9 * CC];         // s8 high weights [co][k][ci] (mma path)
__device__ int8_t  g_wlT[9 * 2 * 32 * 64 * 4];// s8 low weights [k][ch][ci4][wn][t][8w] (dp4a, ci<96 used)
__device__ int8_t  g_wlB[9 * CC * 32];        // s8 low weights [k][co][ci 96..127] (mma B path)
__device__ float   g_fsh[CC];                 // fused scale high
__device__ float   g_fsl[CC];                 // fused scale low

__device__ __forceinline__ int dp4a_us(unsigned a, unsigned b, int c) {
    int r;
    asm("dp4a.u32.s32 %0, %1, %2, %3;" : "=r"(r) : "r"(a), "r"(b), "r"(c));
    return r;
}

// ---------------- K1: per-output-channel weight quantization ----------------
__global__ __launch_bounds__(256) void quant_weights_kernel(
    const float* __restrict__ w, const float* __restrict__ as_ptr,
    float nlev, int which)
{
    int co = blockIdx.x;
    int tid = threadIdx.x;
    const float* wc = w + co * (CC * 9);

    float mx = 0.f;
    for (int i = tid; i < CC * 9; i += 256) mx = fmaxf(mx, fabsf(wc[i]));
    __shared__ float red[256];
    red[tid] = mx;
    __syncthreads();
    for (int s = 128; s > 0; s >>= 1) {
        if (tid < s) red[tid] = fmaxf(red[tid], red[tid + s]);
        __syncthreads();
    }
    float s = red[0] / nlev;

    // decomposition for broadcast dp4a layout
    int ch = co >> 6, r = co & 63;
    int wn = r >> 5, r5 = r & 31;
    int nt = r5 >> 3, tt = (r5 >> 1) & 3, wb = r5 & 1;

    for (int i = tid; i < CC * 9; i += 256) {
        float q = rintf(wc[i] / s);
        q = fminf(fmaxf(q, -nlev), nlev);
        int ci = i / 9, k = i % 9;                 // OIHW: i = ci*9 + k
        if (which == 0) {
            g_wh[(co * 9 + k) * CC + ci] = (int8_t)q;
        } else {
            if (ci < 96) {
                int ci4 = ci >> 2;
                int word = (((k * 2 + ch) * 32 + ci4) * 8 + wn * 4 + tt) * 8 + nt * 2 + wb;
                g_wlT[word * 4 + (ci & 3)] = (int8_t)q;
            } else {
                g_wlB[(k * CC + co) * 32 + (ci - 96)] = (int8_t)q;
            }
        }
    }
    if (tid == 0) {
        if (which) g_fsl[co] = s * as_ptr[0];
        else       g_fsh[co] = s * as_ptr[0];
    }
}

// ---------------- K2: predictor mask + activation fake-quant -> NHWC uint8 ----------------
__global__ __launch_bounds__(256) void mask_quant_kernel(
    const float* __restrict__ x,
    const float* __restrict__ ash_p, const float* __restrict__ asl_p)
{
    int bw = blockIdx.x, bh = blockIdx.y, b = blockIdx.z;
    int tid = threadIdx.x;
    int h0 = bh * 8, w0 = bw * 8;

    __shared__ float sx[64][CC + 1];
    __shared__ uint8_t smask[CC];

    for (int i = tid; i < 64 * CC; i += 256) {
        int c = i >> 6, p = i & 63;
        sx[p][c] = x[((b * CC + c) * HH + h0 + (p >> 3)) * WW + w0 + (p & 7)];
    }
    __syncthreads();

    int lane = tid & 31, wrp = tid >> 5;
    for (int j = 0; j < 16; j++) {
        int c = wrp * 16 + j;
        float v = sx[lane][c] + sx[lane + 32][c];
        #pragma unroll
        for (int o = 16; o > 0; o >>= 1) v += __shfl_xor_sync(0xffffffffu, v, o);
        if (lane == 0) smask[c] = (v * (1.0f / 64.0f) >= 0.05f) ? 1 : 0;
    }
    __syncthreads();

    float ash = ash_p[0], asl = asl_p[0];
    for (int i = tid; i < 64 * (CC / 4); i += 256) {
        int p = i >> 5, c4 = (i & 31);
        int hh = h0 + (p >> 3), ww = w0 + (p & 7);
        unsigned qh = 0u, ql = 0u;
        #pragma unroll
        for (int j = 0; j < 4; j++) {
            int c = c4 * 4 + j;
            float v = sx[p][c];
            bool m = smask[c] != 0;
            float fh = fminf(fmaxf(rintf(v / ash), 0.f), 255.f);
            float fl = fminf(fmaxf(rintf(v / asl), 0.f), 15.f);
            unsigned b8h = m ? (unsigned)fh : 0u;
            unsigned b8l = m ? 0u : (unsigned)fl;
            qh |= b8h << (8 * j);
            ql |= b8l << (8 * j);
        }
        int base = ((b * HH + hh) * WW + ww) * (CC / 4) + c4;
        ((unsigned*)g_ah)[base] = qh;
        ((unsigned*)g_al)[base] = ql;
    }
}

// ---------------- K3: hybrid conv3x3 ----------------
// High conv (ci 0..127) + low conv ci 96..127 on tensor pipe (mma, LDSM);
// low conv ci 0..95 on fma pipe (dp4a). accl mirrors mma C layout, so the
// low-conv mma accumulates directly into accl — no exchange.
// CTA: 256 thr, 8 warps (4M x 2N), tile 64 pix x 64 co, 3 CTAs/SM.

#define ROWB 144
#define ACT_H_OFF 0
#define ACT_L_OFF 14400                         // 100*144
#define WH_OFF 28800
#define WH_BUF 9216                             // 64co * 144
#define WL_OFF (28800 + 2 * 9216)               // 47232
#define WL_BUF 6144                             // 24 ci4 * 256B
#define BL_OFF (47232 + 2 * 6144)               // 59520
#define BL_BUF 3072                             // 64co * 48B (32B data + 16B pad)
#define CONV_SMEM (BL_OFF + 2 * 3072)           // 65664

__device__ __forceinline__ void mma_u8s8(int* c, const unsigned* a, unsigned b0, unsigned b1) {
    asm volatile(
        "mma.sync.aligned.m16n8k32.row.col.s32.u8.s8.s32 "
        "{%0,%1,%2,%3}, {%4,%5,%6,%7}, {%8,%9}, {%0,%1,%2,%3};"
        : "+r"(c[0]), "+r"(c[1]), "+r"(c[2]), "+r"(c[3])
        : "r"(a[0]), "r"(a[1]), "r"(a[2]), "r"(a[3]), "r"(b0), "r"(b1));
}

__device__ __forceinline__ void ldsm_x4(unsigned addr, unsigned* r) {
    asm volatile(
        "ldmatrix.sync.aligned.m8n8.x4.shared.b16 {%0,%1,%2,%3}, [%4];"
        : "=r"(r[0]), "=r"(r[1]), "=r"(r[2]), "=r"(r[3]) : "r"(addr));
}

__device__ __forceinline__ void stage_weights(char* smem, int buf, int k, int co0, int tid) {
    unsigned sb = (unsigned)__cvta_generic_to_shared(smem);
    int ch = co0 >> 6;
    #pragma unroll
    for (int j = 0; j < 4; j++) {
        int i = tid + j * 256;
        if (i < 512) {
            // high mma weights: 64 co x 8 c16
            int co = i >> 3, c16 = i & 7;
            const char* src = (const char*)g_wh + ((co0 + co) * 9 + k) * CC + c16 * 16;
            unsigned d = sb + WH_OFF + buf * WH_BUF + co * ROWB + c16 * 16;
            asm volatile("cp.async.cg.shared.global [%0], [%1], 16;" :: "r"(d), "l"(src));
        } else if (i < 896) {
            // low dp4a weights (ci4 0..23): contiguous 6KB slice
            int r = i - 512;
            const char* src = (const char*)g_wlT + (k * 2 + ch) * 8192 + r * 16;
            unsigned d = sb + WL_OFF + buf * WL_BUF + r * 16;
            asm volatile("cp.async.cg.shared.global [%0], [%1], 16;" :: "r"(d), "l"(src));
        } else if (i < 1024) {
            // low mma B weights (ci 96..127): 64 co rows x 32B, 48B smem stride
            int r = i - 896;
            int row = r >> 1, half = r & 1;
            const char* src = (const char*)g_wlB + (k * CC + co0 + row) * 32 + half * 16;
            unsigned d = sb + BL_OFF + buf * BL_BUF + row * 48 + half * 16;
            asm volatile("cp.async.cg.shared.global [%0], [%1], 16;" :: "r"(d), "l"(src));
        }
    }
}

__global__ __launch_bounds__(256, 3) void conv_hybrid_kernel(float* __restrict__ out)
{
    extern __shared__ __align__(16) char smem[];
    unsigned sb32 = (unsigned)__cvta_generic_to_shared(smem);

    int tid = threadIdx.x;
    int bz = blockIdx.z;
    int b = bz >> 1;
    int co0 = (bz & 1) * 64;
    int h0 = blockIdx.y * 8, w0 = blockIdx.x * 8;

    // act halo tiles (both convs): 1600 16B chunks; invalid -> zero store
    #pragma unroll
    for (int j = 0; j < 7; j++) {
        int i = tid + j * 256;
        if (i < 1600) {
            int cv = i / 800, r = i % 800;
            int p = r >> 3, c16 = r & 7;
            int pr = p / 10 - 1 + h0, pc = p % 10 - 1 + w0;
            char* dgen = smem + (cv ? ACT_L_OFF : ACT_H_OFF) + p * ROWB + c16 * 16;
            if (pr >= 0 && pr < HH && pc >= 0 && pc < WW) {
                const char* src = (const char*)(cv ? g_al : g_ah)
                                  + ((size_t)((b * HH + pr) * WW + pc)) * 128 + c16 * 16;
                unsigned d = (unsigned)__cvta_generic_to_shared(dgen);
                asm volatile("cp.async.cg.shared.global [%0], [%1], 16;" :: "r"(d), "l"(src));
            } else {
                *(uint4*)dgen = make_uint4(0u, 0u, 0u, 0u);
            }
        }
    }
    stage_weights(smem, 0, 0, co0, tid);
    asm volatile("cp.async.commit_group;" ::: "memory");

    int lane = tid & 31, warp = tid >> 5;
    int wm = warp >> 1;          // 0..3 : 16-pixel group (rows 2wm, 2wm+1)
    int wn = warp & 1;           // 0..1 : 32-co group
    int g = lane >> 2, t = lane & 3;

    // ldmatrix lane roles (A operand)
    int lg = lane & 7;
    int rsel = (lane >> 3) & 1;
    int hi16 = (lane >> 4) & 1;

    int acch[4][4], accl[4][4];  // [nt][e]; e: 0,1 = row pin0 co,co+1; 2,3 = row pin1
    #pragma unroll
    for (int nt = 0; nt < 4; nt++)
        #pragma unroll
        for (int q = 0; q < 4; q++) { acch[nt][q] = 0; accl[nt][q] = 0; }

    const char* s_al = smem + ACT_L_OFF;
    unsigned bRow  = sb32 + WH_OFF + (unsigned)(wn * 32 + lane) * ROWB;
    unsigned blRow = sb32 + BL_OFF + (unsigned)(wn * 32 + lane) * 48;

    #pragma unroll 1
    for (int k9 = 0; k9 < 9; k9++) {
        asm volatile("cp.async.wait_group 0;" ::: "memory");
        __syncthreads();
        int buf = k9 & 1;
        if (k9 < 8) {
            stage_weights(smem, buf ^ 1, k9 + 1, co0, tid);
            asm volatile("cp.async.commit_group;" ::: "memory");
        }
        int kh = k9 / 3, kw = k9 - kh * 3;

        // ---- high conv: tensor pipe, fragments via LDSM ----
        unsigned arow = (unsigned)(((2 * wm + kh) * 10 + lg + kw + 10 * rsel) * ROWB)
                      + (unsigned)(hi16 * 16);
        unsigned aAddr = sb32 + ACT_H_OFF + arow;
        unsigned bAddr = bRow + (unsigned)(buf * WH_BUF);
        #pragma unroll
        for (int chunk = 0; chunk < 4; chunk++) {
            unsigned a[4], bA[4], bB[4];
            ldsm_x4(aAddr + chunk * 32, a);
            ldsm_x4(bAddr + chunk * 32, bA);
            ldsm_x4(bAddr + chunk * 32 + 16, bB);
            #pragma unroll
            for (int nt = 0; nt < 4; nt++)
                mma_u8s8(acch[nt], a, bA[nt], bB[nt]);
        }

        // ---- low conv ci 96..127: tensor pipe, accumulates into accl ----
        {
            unsigned aL[4], bA[4], bB[4];
            ldsm_x4(sb32 + ACT_L_OFF + arow + 96, aL);
            unsigned blAddr = blRow + (unsigned)(buf * BL_BUF);
            ldsm_x4(blAddr, bA);
            ldsm_x4(blAddr + 16, bB);
            #pragma unroll
            for (int nt = 0; nt < 4; nt++)
                mma_u8s8(accl[nt], aL, bA[nt], bB[nt]);
        }

        // ---- low conv ci 0..95: fma pipe (dp4a), broadcast LDS.128 weights ----
        int pin0 = (2 * wm + kh) * 10 + g + kw;
        int pin1 = pin0 + 10;
        const char* wlb = smem + WL_OFF + buf * WL_BUF + (wn * 4 + t) * 32;
        #pragma unroll
        for (int seg = 0; seg < 6; seg++) {
            uint4 a0 = *(const uint4*)(s_al + pin0 * ROWB + seg * 16);
            uint4 a1 = *(const uint4*)(s_al + pin1 * ROWB + seg * 16);
            const unsigned aw0[4] = {a0.x, a0.y, a0.z, a0.w};
            const unsigned aw1[4] = {a1.x, a1.y, a1.z, a1.w};
            #pragma unroll
            for (int q = 0; q < 4; q++) {
                const char* wp = wlb + (seg * 4 + q) * 256;
                uint4 wv0 = *(const uint4*)wp;
                uint4 wv1 = *(const uint4*)(wp + 16);
                accl[0][0] = dp4a_us(aw0[q], wv0.x, accl[0][0]);
                accl[0][1] = dp4a_us(aw0[q], wv0.y, accl[0][1]);
                accl[1][0] = dp4a_us(aw0[q], wv0.z, accl[1][0]);
                accl[1][1] = dp4a_us(aw0[q], wv0.w, accl[1][1]);
                accl[2][0] = dp4a_us(aw0[q], wv1.x, accl[2][0]);
                accl[2][1] = dp4a_us(aw0[q], wv1.y, accl[2][1]);
                accl[3][0] = dp4a_us(aw0[q], wv1.z, accl[3][0]);
                accl[3][1] = dp4a_us(aw0[q], wv1.w, accl[3][1]);
                accl[0][2] = dp4a_us(aw1[q], wv0.x, accl[0][2]);
                accl[0][3] = dp4a_us(aw1[q], wv0.y, accl[0][3]);
                accl[1][2] = dp4a_us(aw1[q], wv0.z, accl[1][2]);
                accl[1][3] = dp4a_us(aw1[q], wv0.w, accl[1][3]);
                accl[2][2] = dp4a_us(aw1[q], wv1.x, accl[2][2]);
                accl[2][3] = dp4a_us(aw1[q], wv1.y, accl[2][3]);
                accl[3][2] = dp4a_us(aw1[q], wv1.z, accl[3][2]);
                accl[3][3] = dp4a_us(aw1[q], wv1.w, accl[3][3]);
            }
        }
    }

    // epilogue: y = fsh*acc_h + fsl*acc_l -> NCHW fp32
    int p0 = wm * 16 + g;
    int oh0 = h0 + (p0 >> 3), ow = w0 + (p0 & 7);
    int oh1 = oh0 + 1;                               // pin1 row = next image row
    #pragma unroll
    for (int nt = 0; nt < 4; nt++) {
        int cg0 = co0 + wn * 32 + nt * 8 + t * 2;
        float sh0 = g_fsh[cg0],     sl0 = g_fsl[cg0];
        float sh1 = g_fsh[cg0 + 1], sl1 = g_fsl[cg0 + 1];
        out[((b * CC + cg0) * HH + oh0) * WW + ow] =
            sh0 * (float)acch[nt][0] + sl0 * (float)accl[nt][0];
        out[((b * CC + cg0 + 1) * HH + oh0) * WW + ow] =
            sh1 * (float)acch[nt][1] + sl1 * (float)accl[nt][1];
        out[((b * CC + cg0) * HH + oh1) * WW + ow] =
            sh0 * (float)acch[nt][2] + sl0 * (float)accl[nt][2];
        out[((b * CC + cg0 + 1) * HH + oh1) * WW + ow] =
            sh1 * (float)acch[nt][3] + sl1 * (float)accl[nt][3];
    }
}

// ---------------- launch ----------------
extern "C" void kernel_launch(void* const* d_in, const int* in_sizes, int n_in,
                              void* d_out, int out_size)
{
    const float* x      = (const float*)d_in[0];
    const float* w_high = (const float*)d_in[1];
    const float* w_low  = (const float*)d_in[2];
    const float* as_h   = (const float*)d_in[3];
    const float* as_l   = (const float*)d_in[4];
    float* out = (float*)d_out;

    cudaFuncSetAttribute(conv_hybrid_kernel,
                         cudaFuncAttributeMaxDynamicSharedMemorySize, CONV_SMEM);

    quant_weights_kernel<<<CC, 256>>>(w_high, as_h, 127.0f, 0);
    quant_weights_kernel<<<CC, 256>>>(w_low,  as_l,   7.0f, 1);
    mask_quant_kernel<<<dim3(WW / 8, HH / 8, BB), 256>>>(x, as_h, as_l);
    conv_hybrid_kernel<<<dim3(WW / 8, HH / 8, BB * 2), 256, CONV_SMEM>>>(out);
}

// round 14
// speedup vs baseline: 1.2189x; 1.0398x over previous
#include <cuda_runtime.h>
#include <cstdint>

#define BB 32
#define CC 128
#define HH 56
#define WW 56

// ---------------- scratch (module-static device memory; no allocs) ----------------
__device__ uint8_t g_ah[BB * HH * WW * CC];   // u8 high acts, NHWC (128 B/pixel)
__device__ uint8_t g_al[BB * HH * WW * CC];   // u8 low  acts, NHWC (128 B/pixel)
__device__ int8_t  g_wh[CC * 9 * CC];         // s8 high weights [co][k][ci] (mma path)
__device__ int8_t  g_wlT[9 * 2 * 32 * 64 * 4];// s8 low weights [k][ch][ci4][wn][t][8w] (dp4a, ci<96)
__device__ int8_t  g_wlB[9 * CC * 32];        // s8 low weights [k][co][ci 96..127] (mma B path)
__device__ float   g_fsh[CC];                 // fused scale high
__device__ float   g_fsl[CC];                 // fused scale low

__device__ __forceinline__ int dp4a_us(unsigned a, unsigned b, int c) {
    int r;
    asm("dp4a.u32.s32 %0, %1, %2, %3;" : "=r"(r) : "r"(a), "r"(b), "r"(c));
    return r;
}

// ---------------- K1: per-output-channel weight quantization (both tensors, 1 launch) ----------------
__global__ __launch_bounds__(256) void quant_weights_kernel(
    const float* __restrict__ w_high, const float* __restrict__ w_low,
    const float* __restrict__ ash_p, const float* __restrict__ asl_p)
{
    int which = blockIdx.x >> 7;               // 0: high, 1: low
    int co = blockIdx.x & 127;
    int tid = threadIdx.x;
    const float* wc = (which ? w_low : w_high) + co * (CC * 9);
    float nlev = which ? 7.0f : 127.0f;

    float mx = 0.f;
    for (int i = tid; i < CC * 9; i += 256) mx = fmaxf(mx, fabsf(wc[i]));
    __shared__ float red[256];
    red[tid] = mx;
    __syncthreads();
    for (int s = 128; s > 0; s >>= 1) {
        if (tid < s) red[tid] = fmaxf(red[tid], red[tid + s]);
        __syncthreads();
    }
    float s = red[0] / nlev;

    // decomposition for broadcast dp4a layout
    int ch = co >> 6, r = co & 63;
    int wn = r >> 5, r5 = r & 31;
    int nt = r5 >> 3, tt = (r5 >> 1) & 3, wb = r5 & 1;

    for (int i = tid; i < CC * 9; i += 256) {
        float q = rintf(wc[i] / s);
        q = fminf(fmaxf(q, -nlev), nlev);
        int ci = i / 9, k = i % 9;                 // OIHW: i = ci*9 + k
        if (which == 0) {
            g_wh[(co * 9 + k) * CC + ci] = (int8_t)q;
        } else {
            if (ci < 96) {
                int ci4 = ci >> 2;
                int word = (((k * 2 + ch) * 32 + ci4) * 8 + wn * 4 + tt) * 8 + nt * 2 + wb;
                g_wlT[word * 4 + (ci & 3)] = (int8_t)q;
            } else {
                g_wlB[(k * CC + co) * 32 + (ci - 96)] = (int8_t)q;
            }
        }
    }
    if (tid == 0) {
        if (which) g_fsl[co] = s * asl_p[0];
        else       g_fsh[co] = s * ash_p[0];
    }
}

// ---------------- K2: predictor mask + activation fake-quant -> NHWC uint8 ----------------
__global__ __launch_bounds__(256) void mask_quant_kernel(
    const float* __restrict__ x,
    const float* __restrict__ ash_p, const float* __restrict__ asl_p)
{
    int bw = blockIdx.x, bh = blockIdx.y, b = blockIdx.z;
    int tid = threadIdx.x;
    int h0 = bh * 8, w0 = bw * 8;

    __shared__ float sx[64][CC + 1];
    __shared__ uint8_t smask[CC];

    for (int i = tid; i < 64 * CC; i += 256) {
        int c = i >> 6, p = i & 63;
        sx[p][c] = x[((b * CC + c) * HH + h0 + (p >> 3)) * WW + w0 + (p & 7)];
    }
    __syncthreads();

    int lane = tid & 31, wrp = tid >> 5;
    for (int j = 0; j < 16; j++) {
        int c = wrp * 16 + j;
        float v = sx[lane][c] + sx[lane + 32][c];
        #pragma unroll
        for (int o = 16; o > 0; o >>= 1) v += __shfl_xor_sync(0xffffffffu, v, o);
        if (lane == 0) smask[c] = (v * (1.0f / 64.0f) >= 0.05f) ? 1 : 0;
    }
    __syncthreads();

    float ash = ash_p[0], asl = asl_p[0];
    for (int i = tid; i < 64 * (CC / 4); i += 256) {
        int p = i >> 5, c4 = (i & 31);
        int hh = h0 + (p >> 3), ww = w0 + (p & 7);
        unsigned qh = 0u, ql = 0u;
        #pragma unroll
        for (int j = 0; j < 4; j++) {
            int c = c4 * 4 + j;
            float v = sx[p][c];
            bool m = smask[c] != 0;
            float fh = fminf(fmaxf(rintf(v / ash), 0.f), 255.f);
            float fl = fminf(fmaxf(rintf(v / asl), 0.f), 15.f);
            unsigned b8h = m ? (unsigned)fh : 0u;
            unsigned b8l = m ? 0u : (unsigned)fl;
            qh |= b8h << (8 * j);
            ql |= b8l << (8 * j);
        }
        int base = ((b * HH + hh) * WW + ww) * (CC / 4) + c4;
        ((unsigned*)g_ah)[base] = qh;
        ((unsigned*)g_al)[base] = ql;
    }
}

// ---------------- K3: hybrid conv3x3, pipe-interleaved ----------------
// High conv (ci 0..127) + low conv ci 96..127 on tensor pipe (mma, LDSM);
// low conv ci 0..95 on fma pipe (dp4a). Tap body interleaves one dp4a segment
// after each mma group so both pipes stay fed from every warp's stream.
// CTA: 256 thr, 8 warps (4M x 2N), tile 64 pix x 64 co, 3 CTAs/SM.

#define ROWB 144
#define ACT_H_OFF 0
#define ACT_L_OFF 14400                         // 100*144
#define WH_OFF 28800
#define WH_BUF 9216                             // 64co * 144
#define WL_OFF (28800 + 2 * 9216)               // 47232
#define WL_BUF 6144                             // 24 ci4 * 256B
#define BL_OFF (47232 + 2 * 6144)               // 59520
#define BL_BUF 3072                             // 64co * 48B (32B data + 16B pad)
#define CONV_SMEM (BL_OFF + 2 * 3072)           // 65664

__device__ __forceinline__ void mma_u8s8(int* c, const unsigned* a, unsigned b0, unsigned b1) {
    asm volatile(
        "mma.sync.aligned.m16n8k32.row.col.s32.u8.s8.s32 "
        "{%0,%1,%2,%3}, {%4,%5,%6,%7}, {%8,%9}, {%0,%1,%2,%3};"
        : "+r"(c[0]), "+r"(c[1]), "+r"(c[2]), "+r"(c[3])
        : "r"(a[0]), "r"(a[1]), "r"(a[2]), "r"(a[3]), "r"(b0), "r"(b1));
}

__device__ __forceinline__ void ldsm_x4(unsigned addr, unsigned* r) {
    asm volatile(
        "ldmatrix.sync.aligned.m8n8.x4.shared.b16 {%0,%1,%2,%3}, [%4];"
        : "=r"(r[0]), "=r"(r[1]), "=r"(r[2]), "=r"(r[3]) : "r"(addr));
}

__device__ __forceinline__ void stage_weights(char* smem, int buf, int k, int co0, int tid) {
    unsigned sb = (unsigned)__cvta_generic_to_shared(smem);
    int ch = co0 >> 6;
    #pragma unroll
    for (int j = 0; j < 4; j++) {
        int i = tid + j * 256;
        if (i < 512) {
            int co = i >> 3, c16 = i & 7;
            const char* src = (const char*)g_wh + ((co0 + co) * 9 + k) * CC + c16 * 16;
            unsigned d = sb + WH_OFF + buf * WH_BUF + co * ROWB + c16 * 16;
            asm volatile("cp.async.cg.shared.global [%0], [%1], 16;" :: "r"(d), "l"(src));
        } else if (i < 896) {
            int r = i - 512;
            const char* src = (const char*)g_wlT + (k * 2 + ch) * 8192 + r * 16;
            unsigned d = sb + WL_OFF + buf * WL_BUF + r * 16;
            asm volatile("cp.async.cg.shared.global [%0], [%1], 16;" :: "r"(d), "l"(src));
        } else if (i < 1024) {
            int r = i - 896;
            int row = r >> 1, half = r & 1;
            const char* src = (const char*)g_wlB + (k * CC + co0 + row) * 32 + half * 16;
            unsigned d = sb + BL_OFF + buf * BL_BUF + row * 48 + half * 16;
            asm volatile("cp.async.cg.shared.global [%0], [%1], 16;" :: "r"(d), "l"(src));
        }
    }
}

// one dp4a segment (ci4 = seg*4 .. seg*4+3): 64 dp4a into accl
#define DP4A_SEG(seg)                                                         \
    {                                                                         \
        uint4 a0 = *(const uint4*)(s_al + pin0 * ROWB + (seg) * 16);          \
        uint4 a1 = *(const uint4*)(s_al + pin1 * ROWB + (seg) * 16);          \
        const unsigned aw0[4] = {a0.x, a0.y, a0.z, a0.w};                     \
        const unsigned aw1[4] = {a1.x, a1.y, a1.z, a1.w};                     \
        _Pragma("unroll")                                                     \
        for (int q = 0; q < 4; q++) {                                         \
            const char* wp = wlb + ((seg) * 4 + q) * 256;                     \
            uint4 wv0 = *(const uint4*)wp;                                    \
            uint4 wv1 = *(const uint4*)(wp + 16);                             \
            accl[0][0] = dp4a_us(aw0[q], wv0.x, accl[0][0]);                  \
            accl[0][1] = dp4a_us(aw0[q], wv0.y, accl[0][1]);                  \
            accl[1][0] = dp4a_us(aw0[q], wv0.z, accl[1][0]);                  \
            accl[1][1] = dp4a_us(aw0[q], wv0.w, accl[1][1]);                  \
            accl[2][0] = dp4a_us(aw0[q], wv1.x, accl[2][0]);                  \
            accl[2][1] = dp4a_us(aw0[q], wv1.y, accl[2][1]);                  \
            accl[3][0] = dp4a_us(aw0[q], wv1.z, accl[3][0]);                  \
            accl[3][1] = dp4a_us(aw0[q], wv1.w, accl[3][1]);                  \
            accl[0][2] = dp4a_us(aw1[q], wv0.x, accl[0][2]);                  \
            accl[0][3] = dp4a_us(aw1[q], wv0.y, accl[0][3]);                  \
            accl[1][2] = dp4a_us(aw1[q], wv0.z, accl[1][2]);                  \
            accl[1][3] = dp4a_us(aw1[q], wv0.w, accl[1][3]);                  \
            accl[2][2] = dp4a_us(aw1[q], wv1.x, accl[2][2]);                  \
            accl[2][3] = dp4a_us(aw1[q], wv1.y, accl[2][3]);                  \
            accl[3][2] = dp4a_us(aw1[q], wv1.z, accl[3][2]);                  \
            accl[3][3] = dp4a_us(aw1[q], wv1.w, accl[3][3]);                  \
        }                                                                     \
    }

__global__ __launch_bounds__(256, 3) void conv_hybrid_kernel(float* __restrict__ out)
{
    extern __shared__ __align__(16) char smem[];
    unsigned sb32 = (unsigned)__cvta_generic_to_shared(smem);

    int tid = threadIdx.x;
    int bz = blockIdx.z;
    int b = bz >> 1;
    int co0 = (bz & 1) * 64;
    int h0 = blockIdx.y * 8, w0 = blockIdx.x * 8;

    // act halo tiles (both convs): 1600 16B chunks; invalid -> zero store
    #pragma unroll
    for (int j = 0; j < 7; j++) {
        int i = tid + j * 256;
        if (i < 1600) {
            int cv = i / 800, r = i % 800;
            int p = r >> 3, c16 = r & 7;
            int pr = p / 10 - 1 + h0, pc = p % 10 - 1 + w0;
            char* dgen = smem + (cv ? ACT_L_OFF : ACT_H_OFF) + p * ROWB + c16 * 16;
            if (pr >= 0 && pr < HH && pc >= 0 && pc < WW) {
                const char* src = (const char*)(cv ? g_al : g_ah)
                                  + ((size_t)((b * HH + pr) * WW + pc)) * 128 + c16 * 16;
                unsigned d = (unsigned)__cvta_generic_to_shared(dgen);
                asm volatile("cp.async.cg.shared.global [%0], [%1], 16;" :: "r"(d), "l"(src));
            } else {
                *(uint4*)dgen = make_uint4(0u, 0u, 0u, 0u);
            }
        }
    }
    stage_weights(smem, 0, 0, co0, tid);
    asm volatile("cp.async.commit_group;" ::: "memory");

    int lane = tid & 31, warp = tid >> 5;
    int wm = warp >> 1;          // 0..3 : 16-pixel group (rows 2wm, 2wm+1)
    int wn = warp & 1;           // 0..1 : 32-co group
    int g = lane >> 2, t = lane & 3;

    // ldmatrix lane roles (A operand)
    int lg = lane & 7;
    int rsel = (lane >> 3) & 1;
    int hi16 = (lane >> 4) & 1;

    int acch[4][4], accl[4][4];  // [nt][e]; e: 0,1 = row pin0 co,co+1; 2,3 = row pin1
    #pragma unroll
    for (int nt = 0; nt < 4; nt++)
        #pragma unroll
        for (int q = 0; q < 4; q++) { acch[nt][q] = 0; accl[nt][q] = 0; }

    const char* s_al = smem + ACT_L_OFF;
    unsigned bRow  = sb32 + WH_OFF + (unsigned)(wn * 32 + lane) * ROWB;
    unsigned blRow = sb32 + BL_OFF + (unsigned)(wn * 32 + lane) * 48;

    #pragma unroll 1
    for (int k9 = 0; k9 < 9; k9++) {
        asm volatile("cp.async.wait_group 0;" ::: "memory");
        __syncthreads();
        int buf = k9 & 1;
        if (k9 < 8) {
            stage_weights(smem, buf ^ 1, k9 + 1, co0, tid);
            asm volatile("cp.async.commit_group;" ::: "memory");
        }
        int kh = k9 / 3, kw = k9 - kh * 3;

        unsigned arow = (unsigned)(((2 * wm + kh) * 10 + lg + kw + 10 * rsel) * ROWB)
                      + (unsigned)(hi16 * 16);
        unsigned aAddr = sb32 + ACT_H_OFF + arow;
        unsigned bAddr = bRow + (unsigned)(buf * WH_BUF);
        int pin0 = (2 * wm + kh) * 10 + g + kw;
        int pin1 = pin0 + 10;
        const char* wlb = smem + WL_OFF + buf * WL_BUF + (wn * 4 + t) * 32;

        // ---- interleaved: each mma group followed by one dp4a segment ----
        #pragma unroll
        for (int chunk = 0; chunk < 4; chunk++) {
            unsigned a[4], bA[4], bB[4];
            ldsm_x4(aAddr + chunk * 32, a);
            ldsm_x4(bAddr + chunk * 32, bA);
            ldsm_x4(bAddr + chunk * 32 + 16, bB);
            #pragma unroll
            for (int nt = 0; nt < 4; nt++)
                mma_u8s8(acch[nt], a, bA[nt], bB[nt]);
            DP4A_SEG(chunk);
        }
        {
            unsigned aL[4], bA[4], bB[4];
            ldsm_x4(sb32 + ACT_L_OFF + arow + 96, aL);
            unsigned blAddr = blRow + (unsigned)(buf * BL_BUF);
            ldsm_x4(blAddr, bA);
            ldsm_x4(blAddr + 16, bB);
            #pragma unroll
            for (int nt = 0; nt < 4; nt++)
                mma_u8s8(accl[nt], aL, bA[nt], bB[nt]);
            DP4A_SEG(4);
            DP4A_SEG(5);
        }
    }

    // epilogue: y = fsh*acc_h + fsl*acc_l -> NCHW fp32
    int p0 = wm * 16 + g;
    int oh0 = h0 + (p0 >> 3), ow = w0 + (p0 & 7);
    int oh1 = oh0 + 1;                               // pin1 row = next image row
    #pragma unroll
    for (int nt = 0; nt < 4; nt++) {
        int cg0 = co0 + wn * 32 + nt * 8 + t * 2;
        float sh0 = g_fsh[cg0],     sl0 = g_fsl[cg0];
        float sh1 = g_fsh[cg0 + 1], sl1 = g_fsl[cg0 + 1];
        out[((b * CC + cg0) * HH + oh0) * WW + ow] =
            sh0 * (float)acch[nt][0] + sl0 * (float)accl[nt][0];
        out[((b * CC + cg0 + 1) * HH + oh0) * WW + ow] =
            sh1 * (float)acch[nt][1] + sl1 * (float)accl[nt][1];
        out[((b * CC + cg0) * HH + oh1) * WW + ow] =
            sh0 * (float)acch[nt][2] + sl0 * (float)accl[nt][2];
        out[((b * CC + cg0 + 1) * HH + oh1) * WW + ow] =
            sh1 * (float)acch[nt][3] + sl1 * (float)accl[nt][3];
    }
}

// ---------------- launch ----------------
extern "C" void kernel_launch(void* const* d_in, const int* in_sizes, int n_in,
                              void* d_out, int out_size)
{
    const float* x      = (const float*)d_in[0];
    const float* w_high = (const float*)d_in[1];
    const float* w_low  = (const float*)d_in[2];
    const float* as_h   = (const float*)d_in[3];
    const float* as_l   = (const float*)d_in[4];
    float* out = (float*)d_out;

    cudaFuncSetAttribute(conv_hybrid_kernel,
                         cudaFuncAttributeMaxDynamicSharedMemorySize, CONV_SMEM);

    quant_weights_kernel<<<2 * CC, 256>>>(w_high, w_low, as_h, as_l);
    mask_quant_kernel<<<dim3(WW / 8, HH / 8, BB), 256>>>(x, as_h, as_l);
    conv_hybrid_kernel<<<dim3(WW / 8, HH / 8, BB * 2), 256, CONV_SMEM>>>(out);
}

// round 15
// speedup vs baseline: 1.2315x; 1.0103x over previous
#include <cuda_runtime.h>
#include <cstdint>

#define BB 32
#define CC 128
#define HH 56
#define WW 56

// ---------------- scratch (module-static device memory; no allocs) ----------------
__device__ uint8_t g_ah[BB * HH * WW * CC];   // u8 high acts, NHWC (128 B/pixel)
__device__ uint8_t g_al[BB * HH * WW * CC];   // u8 low  acts, NHWC (128 B/pixel)
__device__ int8_t  g_wh[CC * 9 * CC];         // s8 high weights [co][k][ci] (mma path)
__device__ int8_t  g_wlT[9 * 2 * 32 * 64 * 4];// s8 low weights [k][ch][ci4][wn][t][8w] (dp4a, ci<96)
__device__ int8_t  g_wlB[9 * CC * 32];        // s8 low weights [k][co][ci 96..127] (mma B path)
__device__ float   g_fsh[CC];                 // fused scale high
__device__ float   g_fsl[CC];                 // fused scale low

__device__ __forceinline__ int dp4a_us(unsigned a, unsigned b, int c) {
    int r;
    asm("dp4a.u32.s32 %0, %1, %2, %3;" : "=r"(r) : "r"(a), "r"(b), "r"(c));
    return r;
}

// ---------------- K1: per-output-channel weight quantization (both tensors, 1 launch) ----------------
__global__ __launch_bounds__(256) void quant_weights_kernel(
    const float* __restrict__ w_high, const float* __restrict__ w_low,
    const float* __restrict__ ash_p, const float* __restrict__ asl_p)
{
    int which = blockIdx.x >> 7;               // 0: high, 1: low
    int co = blockIdx.x & 127;
    int tid = threadIdx.x;
    const float* wc = (which ? w_low : w_high) + co * (CC * 9);
    float nlev = which ? 7.0f : 127.0f;

    float mx = 0.f;
    for (int i = tid; i < CC * 9; i += 256) mx = fmaxf(mx, fabsf(wc[i]));
    __shared__ float red[256];
    red[tid] = mx;
    __syncthreads();
    for (int s = 128; s > 0; s >>= 1) {
        if (tid < s) red[tid] = fmaxf(red[tid], red[tid + s]);
        __syncthreads();
    }
    float s = red[0] / nlev;

    // decomposition for broadcast dp4a layout
    int ch = co >> 6, r = co & 63;
    int wn = r >> 5, r5 = r & 31;
    int nt = r5 >> 3, tt = (r5 >> 1) & 3, wb = r5 & 1;

    for (int i = tid; i < CC * 9; i += 256) {
        float q = rintf(wc[i] / s);
        q = fminf(fmaxf(q, -nlev), nlev);
        int ci = i / 9, k = i % 9;                 // OIHW: i = ci*9 + k
        if (which == 0) {
            g_wh[(co * 9 + k) * CC + ci] = (int8_t)q;
        } else {
            if (ci < 96) {
                int ci4 = ci >> 2;
                int word = (((k * 2 + ch) * 32 + ci4) * 8 + wn * 4 + tt) * 8 + nt * 2 + wb;
                g_wlT[word * 4 + (ci & 3)] = (int8_t)q;
            } else {
                g_wlB[(k * CC + co) * 32 + (ci - 96)] = (int8_t)q;
            }
        }
    }
    if (tid == 0) {
        if (which) g_fsl[co] = s * asl_p[0];
        else       g_fsh[co] = s * ash_p[0];
    }
}

// ---------------- K2: predictor mask + activation fake-quant -> NHWC uint8 ----------------
// Hoisted reciprocals (no per-element div) + LDG.128 fill loop.
__global__ __launch_bounds__(256) void mask_quant_kernel(
    const float* __restrict__ x,
    const float* __restrict__ ash_p, const float* __restrict__ asl_p)
{
    int bw = blockIdx.x, bh = blockIdx.y, b = blockIdx.z;
    int tid = threadIdx.x;
    int h0 = bh * 8, w0 = bw * 8;

    __shared__ float sx[64][CC + 1];
    __shared__ uint8_t smask[CC];

    // vectorized fill: i indexes (c, row, half) -> one float4 of 4 consecutive w
    for (int i = tid; i < 64 * CC / 4; i += 256) {
        int c = i >> 4;
        int r = i & 15;
        int row = r >> 1, half = r & 1;
        float4 v = *(const float4*)&x[((size_t)(b * CC + c) * HH + h0 + row) * WW
                                      + w0 + half * 4];
        int p = row * 8 + half * 4;
        sx[p + 0][c] = v.x;
        sx[p + 1][c] = v.y;
        sx[p + 2][c] = v.z;
        sx[p + 3][c] = v.w;
    }
    __syncthreads();

    int lane = tid & 31, wrp = tid >> 5;
    for (int j = 0; j < 16; j++) {
        int c = wrp * 16 + j;
        float v = sx[lane][c] + sx[lane + 32][c];
        #pragma unroll
        for (int o = 16; o > 0; o >>= 1) v += __shfl_xor_sync(0xffffffffu, v, o);
        if (lane == 0) smask[c] = (v * (1.0f / 64.0f) >= 0.05f) ? 1 : 0;
    }
    __syncthreads();

    float rash = 1.0f / ash_p[0];
    float rasl = 1.0f / asl_p[0];
    for (int i = tid; i < 64 * (CC / 4); i += 256) {
        int p = i >> 5, c4 = (i & 31);
        int hh = h0 + (p >> 3), ww = w0 + (p & 7);
        unsigned qh = 0u, ql = 0u;
        #pragma unroll
        for (int j = 0; j < 4; j++) {
            int c = c4 * 4 + j;
            float v = sx[p][c];
            bool m = smask[c] != 0;
            float fh = fminf(fmaxf(rintf(v * rash), 0.f), 255.f);
            float fl = fminf(fmaxf(rintf(v * rasl), 0.f), 15.f);
            unsigned b8h = m ? (unsigned)fh : 0u;
            unsigned b8l = m ? 0u : (unsigned)fl;
            qh |= b8h << (8 * j);
            ql |= b8l << (8 * j);
        }
        int base = ((b * HH + hh) * WW + ww) * (CC / 4) + c4;
        ((unsigned*)g_ah)[base] = qh;
        ((unsigned*)g_al)[base] = ql;
    }
}

// ---------------- K3: hybrid conv3x3, pipe-interleaved (unchanged from R14) ----------------
#define ROWB 144
#define ACT_H_OFF 0
#define ACT_L_OFF 14400                         // 100*144
#define WH_OFF 28800
#define WH_BUF 9216                             // 64co * 144
#define WL_OFF (28800 + 2 * 9216)               // 47232
#define WL_BUF 6144                             // 24 ci4 * 256B
#define BL_OFF (47232 + 2 * 6144)               // 59520
#define BL_BUF 3072                             // 64co * 48B (32B data + 16B pad)
#define CONV_SMEM (BL_OFF + 2 * 3072)           // 65664

__device__ __forceinline__ void mma_u8s8(int* c, const unsigned* a, unsigned b0, unsigned b1) {
    asm volatile(
        "mma.sync.aligned.m16n8k32.row.col.s32.u8.s8.s32 "
        "{%0,%1,%2,%3}, {%4,%5,%6,%7}, {%8,%9}, {%0,%1,%2,%3};"
        : "+r"(c[0]), "+r"(c[1]), "+r"(c[2]), "+r"(c[3])
        : "r"(a[0]), "r"(a[1]), "r"(a[2]), "r"(a[3]), "r"(b0), "r"(b1));
}

__device__ __forceinline__ void ldsm_x4(unsigned addr, unsigned* r) {
    asm volatile(
        "ldmatrix.sync.aligned.m8n8.x4.shared.b16 {%0,%1,%2,%3}, [%4];"
        : "=r"(r[0]), "=r"(r[1]), "=r"(r[2]), "=r"(r[3]) : "r"(addr));
}

__device__ __forceinline__ void stage_weights(char* smem, int buf, int k, int co0, int tid) {
    unsigned sb = (unsigned)__cvta_generic_to_shared(smem);
    int ch = co0 >> 6;
    #pragma unroll
    for (int j = 0; j < 4; j++) {
        int i = tid + j * 256;
        if (i < 512) {
            int co = i >> 3, c16 = i & 7;
            const char* src = (const char*)g_wh + ((co0 + co) * 9 + k) * CC + c16 * 16;
            unsigned d = sb + WH_OFF + buf * WH_BUF + co * ROWB + c16 * 16;
            asm volatile("cp.async.cg.shared.global [%0], [%1], 16;" :: "r"(d), "l"(src));
        } else if (i < 896) {
            int r = i - 512;
            const char* src = (const char*)g_wlT + (k * 2 + ch) * 8192 + r * 16;
            unsigned d = sb + WL_OFF + buf * WL_BUF + r * 16;
            asm volatile("cp.async.cg.shared.global [%0], [%1], 16;" :: "r"(d), "l"(src));
        } else if (i < 1024) {
            int r = i - 896;
            int row = r >> 1, half = r & 1;
            const char* src = (const char*)g_wlB + (k * CC + co0 + row) * 32 + half * 16;
            unsigned d = sb + BL_OFF + buf * BL_BUF + row * 48 + half * 16;
            asm volatile("cp.async.cg.shared.global [%0], [%1], 16;" :: "r"(d), "l"(src));
        }
    }
}

// one dp4a segment (ci4 = seg*4 .. seg*4+3): 64 dp4a into accl
#define DP4A_SEG(seg)                                                         \
    {                                                                         \
        uint4 a0 = *(const uint4*)(s_al + pin0 * ROWB + (seg) * 16);          \
        uint4 a1 = *(const uint4*)(s_al + pin1 * ROWB + (seg) * 16);          \
        const unsigned aw0[4] = {a0.x, a0.y, a0.z, a0.w};                     \
        const unsigned aw1[4] = {a1.x, a1.y, a1.z, a1.w};                     \
        _Pragma("unroll")                                                     \
        for (int q = 0; q < 4; q++) {                                         \
            const char* wp = wlb + ((seg) * 4 + q) * 256;                     \
            uint4 wv0 = *(const uint4*)wp;                                    \
            uint4 wv1 = *(const uint4*)(wp + 16);                             \
            accl[0][0] = dp4a_us(aw0[q], wv0.x, accl[0][0]);                  \
            accl[0][1] = dp4a_us(aw0[q], wv0.y, accl[0][1]);                  \
            accl[1][0] = dp4a_us(aw0[q], wv0.z, accl[1][0]);                  \
            accl[1][1] = dp4a_us(aw0[q], wv0.w, accl[1][1]);                  \
            accl[2][0] = dp4a_us(aw0[q], wv1.x, accl[2][0]);                  \
            accl[2][1] = dp4a_us(aw0[q], wv1.y, accl[2][1]);                  \
            accl[3][0] = dp4a_us(aw0[q], wv1.z, accl[3][0]);                  \
            accl[3][1] = dp4a_us(aw0[q], wv1.w, accl[3][1]);                  \
            accl[0][2] = dp4a_us(aw1[q], wv0.x, accl[0][2]);                  \
            accl[0][3] = dp4a_us(aw1[q], wv0.y, accl[0][3]);                  \
            accl[1][2] = dp4a_us(aw1[q], wv0.z, accl[1][2]);                  \
            accl[1][3] = dp4a_us(aw1[q], wv0.w, accl[1][3]);                  \
            accl[2][2] = dp4a_us(aw1[q], wv1.x, accl[2][2]);                  \
            accl[2][3] = dp4a_us(aw1[q], wv1.y, accl[2][3]);                  \
            accl[3][2] = dp4a_us(aw1[q], wv1.z, accl[3][2]);                  \
            accl[3][3] = dp4a_us(aw1[q], wv1.w, accl[3][3]);                  \
        }                                                                     \
    }

__global__ __launch_bounds__(256, 3) void conv_hybrid_kernel(float* __restrict__ out)
{
    extern __shared__ __align__(16) char smem[];
    unsigned sb32 = (unsigned)__cvta_generic_to_shared(smem);

    int tid = threadIdx.x;
    int bz = blockIdx.z;
    int b = bz >> 1;
    int co0 = (bz & 1) * 64;
    int h0 = blockIdx.y * 8, w0 = blockIdx.x * 8;

    // act halo tiles (both convs): 1600 16B chunks; invalid -> zero store
    #pragma unroll
    for (int j = 0; j < 7; j++) {
        int i = tid + j * 256;
        if (i < 1600) {
            int cv = i / 800, r = i % 800;
            int p = r >> 3, c16 = r & 7;
            int pr = p / 10 - 1 + h0, pc = p % 10 - 1 + w0;
            char* dgen = smem + (cv ? ACT_L_OFF : ACT_H_OFF) + p * ROWB + c16 * 16;
            if (pr >= 0 && pr < HH && pc >= 0 && pc < WW) {
                const char* src = (const char*)(cv ? g_al : g_ah)
                                  + ((size_t)((b * HH + pr) * WW + pc)) * 128 + c16 * 16;
                unsigned d = (unsigned)__cvta_generic_to_shared(dgen);
                asm volatile("cp.async.cg.shared.global [%0], [%1], 16;" :: "r"(d), "l"(src));
            } else {
                *(uint4*)dgen = make_uint4(0u, 0u, 0u, 0u);
            }
        }
    }
    stage_weights(smem, 0, 0, co0, tid);
    asm volatile("cp.async.commit_group;" ::: "memory");

    int lane = tid & 31, warp = tid >> 5;
    int wm = warp >> 1;          // 0..3 : 16-pixel group (rows 2wm, 2wm+1)
    int wn = warp & 1;           // 0..1 : 32-co group
    int g = lane >> 2, t = lane & 3;

    // ldmatrix lane roles (A operand)
    int lg = lane & 7;
    int rsel = (lane >> 3) & 1;
    int hi16 = (lane >> 4) & 1;

    int acch[4][4], accl[4][4];  // [nt][e]; e: 0,1 = row pin0 co,co+1; 2,3 = row pin1
    #pragma unroll
    for (int nt = 0; nt < 4; nt++)
        #pragma unroll
        for (int q = 0; q < 4; q++) { acch[nt][q] = 0; accl[nt][q] = 0; }

    const char* s_al = smem + ACT_L_OFF;
    unsigned bRow  = sb32 + WH_OFF + (unsigned)(wn * 32 + lane) * ROWB;
    unsigned blRow = sb32 + BL_OFF + (unsigned)(wn * 32 + lane) * 48;

    #pragma unroll 1
    for (int k9 = 0; k9 < 9; k9++) {
        asm volatile("cp.async.wait_group 0;" ::: "memory");
        __syncthreads();
        int buf = k9 & 1;
        if (k9 < 8) {
            stage_weights(smem, buf ^ 1, k9 + 1, co0, tid);
            asm volatile("cp.async.commit_group;" ::: "memory");
        }
        int kh = k9 / 3, kw = k9 - kh * 3;

        unsigned arow = (unsigned)(((2 * wm + kh) * 10 + lg + kw + 10 * rsel) * ROWB)
                      + (unsigned)(hi16 * 16);
        unsigned aAddr = sb32 + ACT_H_OFF + arow;
        unsigned bAddr = bRow + (unsigned)(buf * WH_BUF);
        int pin0 = (2 * wm + kh) * 10 + g + kw;
        int pin1 = pin0 + 10;
        const char* wlb = smem + WL_OFF + buf * WL_BUF + (wn * 4 + t) * 32;

        // ---- interleaved: each mma group followed by one dp4a segment ----
        #pragma unroll
        for (int chunk = 0; chunk < 4; chunk++) {
            unsigned a[4], bA[4], bB[4];
            ldsm_x4(aAddr + chunk * 32, a);
            ldsm_x4(bAddr + chunk * 32, bA);
            ldsm_x4(bAddr + chunk * 32 + 16, bB);
            #pragma unroll
            for (int nt = 0; nt < 4; nt++)
                mma_u8s8(acch[nt], a, bA[nt], bB[nt]);
            DP4A_SEG(chunk);
        }
        {
            unsigned aL[4], bA[4], bB[4];
            ldsm_x4(sb32 + ACT_L_OFF + arow + 96, aL);
            unsigned blAddr = blRow + (unsigned)(buf * BL_BUF);
            ldsm_x4(blAddr, bA);
            ldsm_x4(blAddr + 16, bB);
            #pragma unroll
            for (int nt = 0; nt < 4; nt++)
                mma_u8s8(accl[nt], aL, bA[nt], bB[nt]);
            DP4A_SEG(4);
            DP4A_SEG(5);
        }
    }

    // epilogue: y = fsh*acc_h + fsl*acc_l -> NCHW fp32
    int p0 = wm * 16 + g;
    int oh0 = h0 + (p0 >> 3), ow = w0 + (p0 & 7);
    int oh1 = oh0 + 1;                               // pin1 row = next image row
    #pragma unroll
    for (int nt = 0; nt < 4; nt++) {
        int cg0 = co0 + wn * 32 + nt * 8 + t * 2;
        float sh0 = g_fsh[cg0],     sl0 = g_fsl[cg0];
        float sh1 = g_fsh[cg0 + 1], sl1 = g_fsl[cg0 + 1];
        out[((b * CC + cg0) * HH + oh0) * WW + ow] =
            sh0 * (float)acch[nt][0] + sl0 * (float)accl[nt][0];
        out[((b * CC + cg0 + 1) * HH + oh0) * WW + ow] =
            sh1 * (float)acch[nt][1] + sl1 * (float)accl[nt][1];
        out[((b * CC + cg0) * HH + oh1) * WW + ow] =
            sh0 * (float)acch[nt][2] + sl0 * (float)accl[nt][2];
        out[((b * CC + cg0 + 1) * HH + oh1) * WW + ow] =
            sh1 * (float)acch[nt][3] + sl1 * (float)accl[nt][3];
    }
}

// ---------------- launch ----------------
extern "C" void kernel_launch(void* const* d_in, const int* in_sizes, int n_in,
                              void* d_out, int out_size)
{
    const float* x      = (const float*)d_in[0];
    const float* w_high = (const float*)d_in[1];
    const float* w_low  = (const float*)d_in[2];
    const float* as_h   = (const float*)d_in[3];
    const float* as_l   = (const float*)d_in[4];
    float* out = (float*)d_out;

    cudaFuncSetAttribute(conv_hybrid_kernel,
                         cudaFuncAttributeMaxDynamicSharedMemorySize, CONV_SMEM);

    quant_weights_kernel<<<2 * CC, 256>>>(w_high, w_low, as_h, as_l);
    mask_quant_kernel<<<dim3(WW / 8, HH / 8, BB), 256>>>(x, as_h, as_l);
    conv_hybrid_kernel<<<dim3(WW / 8, HH / 8, BB * 2), 256, CONV_SMEM>>>(out);
}

// round 16
// speedup vs baseline: 1.2397x; 1.0067x over previous
#include <cuda_runtime.h>
#include <cstdint>

#define BB 32
#define CC 128
#define HH 56
#define WW 56

// ---------------- scratch (module-static device memory; no allocs) ----------------
__device__ uint8_t g_ah[BB * HH * WW * CC];   // u8 high acts, NHWC (128 B/pixel)
__device__ uint8_t g_al[BB * HH * WW * CC];   // u8 low  acts, NHWC (128 B/pixel)
__device__ int8_t  g_wh[CC * 9 * CC];         // s8 high weights [co][k][ci] (mma path)
__device__ int8_t  g_wlT[9 * 2 * 32 * 64 * 4];// s8 low weights [k][ch][ci4][wn][t][8w] (dp4a, ci<96)
__device__ int8_t  g_wlB[9 * CC * 32];        // s8 low weights [k][co][ci 96..127] (mma B path)
__device__ float   g_fsh[CC];                 // fused scale high
__device__ float   g_fsl[CC];                 // fused scale low

__device__ __forceinline__ int dp4a_us(unsigned a, unsigned b, int c) {
    int r;
    asm("dp4a.u32.s32 %0, %1, %2, %3;" : "=r"(r) : "r"(a), "r"(b), "r"(c));
    return r;
}

// ---------------- K1: per-output-channel weight quantization (both tensors, 1 launch) ----------------
__global__ __launch_bounds__(256) void quant_weights_kernel(
    const float* __restrict__ w_high, const float* __restrict__ w_low,
    const float* __restrict__ ash_p, const float* __restrict__ asl_p)
{
    int which = blockIdx.x >> 7;               // 0: high, 1: low
    int co = blockIdx.x & 127;
    int tid = threadIdx.x;
    const float* wc = (which ? w_low : w_high) + co * (CC * 9);
    float nlev = which ? 7.0f : 127.0f;

    float mx = 0.f;
    for (int i = tid; i < CC * 9; i += 256) mx = fmaxf(mx, fabsf(wc[i]));
    __shared__ float red[256];
    red[tid] = mx;
    __syncthreads();
    for (int s = 128; s > 0; s >>= 1) {
        if (tid < s) red[tid] = fmaxf(red[tid], red[tid + s]);
        __syncthreads();
    }
    float s = red[0] / nlev;

    // decomposition for broadcast dp4a layout
    int ch = co >> 6, r = co & 63;
    int wn = r >> 5, r5 = r & 31;
    int nt = r5 >> 3, tt = (r5 >> 1) & 3, wb = r5 & 1;

    for (int i = tid; i < CC * 9; i += 256) {
        float q = rintf(wc[i] / s);
        q = fminf(fmaxf(q, -nlev), nlev);
        int ci = i / 9, k = i % 9;                 // OIHW: i = ci*9 + k
        if (which == 0) {
            g_wh[(co * 9 + k) * CC + ci] = (int8_t)q;
        } else {
            if (ci < 96) {
                int ci4 = ci >> 2;
                int word = (((k * 2 + ch) * 32 + ci4) * 8 + wn * 4 + tt) * 8 + nt * 2 + wb;
                g_wlT[word * 4 + (ci & 3)] = (int8_t)q;
            } else {
                g_wlB[(k * CC + co) * 32 + (ci - 96)] = (int8_t)q;
            }
        }
    }
    if (tid == 0) {
        if (which) g_fsl[co] = s * asl_p[0];
        else       g_fsh[co] = s * ash_p[0];
    }
}

// ---------------- K2: predictor mask + activation fake-quant -> NHWC uint8 ----------------
// Saturating-convert diet: F2I.U32.RNI (negatives -> 0 free) + IMNMX + byte-mask AND.
__global__ __launch_bounds__(256) void mask_quant_kernel(
    const float* __restrict__ x,
    const float* __restrict__ ash_p, const float* __restrict__ asl_p)
{
    int bw = blockIdx.x, bh = blockIdx.y, b = blockIdx.z;
    int tid = threadIdx.x;
    int h0 = bh * 8, w0 = bw * 8;

    __shared__ float sx[64][CC + 1];
    __shared__ uint8_t smask[CC];              // 0xFF (high) / 0x00 (low)

    // vectorized fill: i indexes (c, row, half) -> one float4 of 4 consecutive w
    for (int i = tid; i < 64 * CC / 4; i += 256) {
        int c = i >> 4;
        int r = i & 15;
        int row = r >> 1, half = r & 1;
        float4 v = *(const float4*)&x[((size_t)(b * CC + c) * HH + h0 + row) * WW
                                      + w0 + half * 4];
        int p = row * 8 + half * 4;
        sx[p + 0][c] = v.x;
        sx[p + 1][c] = v.y;
        sx[p + 2][c] = v.z;
        sx[p + 3][c] = v.w;
    }
    __syncthreads();

    int lane = tid & 31, wrp = tid >> 5;
    for (int j = 0; j < 16; j++) {
        int c = wrp * 16 + j;
        float v = sx[lane][c] + sx[lane + 32][c];
        #pragma unroll
        for (int o = 16; o > 0; o >>= 1) v += __shfl_xor_sync(0xffffffffu, v, o);
        if (lane == 0) smask[c] = (v * (1.0f / 64.0f) >= 0.05f) ? 0xFF : 0x00;
    }
    __syncthreads();

    float rash = 1.0f / ash_p[0];
    float rasl = 1.0f / asl_p[0];
    for (int i = tid; i < 64 * (CC / 4); i += 256) {
        int p = i >> 5, c4 = (i & 31);
        int hh = h0 + (p >> 3), ww = w0 + (p & 7);
        unsigned mu = ((const unsigned*)smask)[c4];   // 4 channel byte-masks
        unsigned qh = 0u, ql = 0u;
        #pragma unroll
        for (int j = 0; j < 4; j++) {
            float v = sx[p][c4 * 4 + j];
            // F2I.U32.RNI saturates negatives to 0; round-half-even matches jnp.round
            unsigned uh = umin(__float2uint_rn(v * rash), 255u);
            unsigned ul = umin(__float2uint_rn(v * rasl), 15u);
            qh |= uh << (8 * j);
            ql |= ul << (8 * j);
        }
        qh &= mu;                                     // high: keep masked-in channels
        ql &= ~mu;                                    // low: keep masked-out channels
        int base = ((b * HH + hh) * WW + ww) * (CC / 4) + c4;
        ((unsigned*)g_ah)[base] = qh;
        ((unsigned*)g_al)[base] = ql;
    }
}

// ---------------- K3: hybrid conv3x3, pipe-interleaved (unchanged from R15) ----------------
#define ROWB 144
#define ACT_H_OFF 0
#define ACT_L_OFF 14400                         // 100*144
#define WH_OFF 28800
#define WH_BUF 9216                             // 64co * 144
#define WL_OFF (28800 + 2 * 9216)               // 47232
#define WL_BUF 6144                             // 24 ci4 * 256B
#define BL_OFF (47232 + 2 * 6144)               // 59520
#define BL_BUF 3072                             // 64co * 48B (32B data + 16B pad)
#define CONV_SMEM (BL_OFF + 2 * 3072)           // 65664

__device__ __forceinline__ void mma_u8s8(int* c, const unsigned* a, unsigned b0, unsigned b1) {
    asm volatile(
        "mma.sync.aligned.m16n8k32.row.col.s32.u8.s8.s32 "
        "{%0,%1,%2,%3}, {%4,%5,%6,%7}, {%8,%9}, {%0,%1,%2,%3};"
        : "+r"(c[0]), "+r"(c[1]), "+r"(c[2]), "+r"(c[3])
        : "r"(a[0]), "r"(a[1]), "r"(a[2]), "r"(a[3]), "r"(b0), "r"(b1));
}

__device__ __forceinline__ void ldsm_x4(unsigned addr, unsigned* r) {
    asm volatile(
        "ldmatrix.sync.aligned.m8n8.x4.shared.b16 {%0,%1,%2,%3}, [%4];"
        : "=r"(r[0]), "=r"(r[1]), "=r"(r[2]), "=r"(r[3]) : "r"(addr));
}

__device__ __forceinline__ void stage_weights(char* smem, int buf, int k, int co0, int tid) {
    unsigned sb = (unsigned)__cvta_generic_to_shared(smem);
    int ch = co0 >> 6;
    #pragma unroll
    for (int j = 0; j < 4; j++) {
        int i = tid + j * 256;
        if (i < 512) {
            int co = i >> 3, c16 = i & 7;
            const char* src = (const char*)g_wh + ((co0 + co) * 9 + k) * CC + c16 * 16;
            unsigned d = sb + WH_OFF + buf * WH_BUF + co * ROWB + c16 * 16;
            asm volatile("cp.async.cg.shared.global [%0], [%1], 16;" :: "r"(d), "l"(src));
        } else if (i < 896) {
            int r = i - 512;
            const char* src = (const char*)g_wlT + (k * 2 + ch) * 8192 + r * 16;
            unsigned d = sb + WL_OFF + buf * WL_BUF + r * 16;
            asm volatile("cp.async.cg.shared.global [%0], [%1], 16;" :: "r"(d), "l"(src));
        } else if (i < 1024) {
            int r = i - 896;
            int row = r >> 1, half = r & 1;
            const char* src = (const char*)g_wlB + (k * CC + co0 + row) * 32 + half * 16;
            unsigned d = sb + BL_OFF + buf * BL_BUF + row * 48 + half * 16;
            asm volatile("cp.async.cg.shared.global [%0], [%1], 16;" :: "r"(d), "l"(src));
        }
    }
}

// one dp4a segment (ci4 = seg*4 .. seg*4+3): 64 dp4a into accl
#define DP4A_SEG(seg)                                                         \
    {                                                                         \
        uint4 a0 = *(const uint4*)(s_al + pin0 * ROWB + (seg) * 16);          \
        uint4 a1 = *(const uint4*)(s_al + pin1 * ROWB + (seg) * 16);          \
        const unsigned aw0[4] = {a0.x, a0.y, a0.z, a0.w};                     \
        const unsigned aw1[4] = {a1.x, a1.y, a1.z, a1.w};                     \
        _Pragma("unroll")                                                     \
        for (int q = 0; q < 4; q++) {                                         \
            const char* wp = wlb + ((seg) * 4 + q) * 256;                     \
            uint4 wv0 = *(const uint4*)wp;                                    \
            uint4 wv1 = *(const uint4*)(wp + 16);                             \
            accl[0][0] = dp4a_us(aw0[q], wv0.x, accl[0][0]);                  \
            accl[0][1] = dp4a_us(aw0[q], wv0.y, accl[0][1]);                  \
            accl[1][0] = dp4a_us(aw0[q], wv0.z, accl[1][0]);                  \
            accl[1][1] = dp4a_us(aw0[q], wv0.w, accl[1][1]);                  \
            accl[2][0] = dp4a_us(aw0[q], wv1.x, accl[2][0]);                  \
            accl[2][1] = dp4a_us(aw0[q], wv1.y, accl[2][1]);                  \
            accl[3][0] = dp4a_us(aw0[q], wv1.z, accl[3][0]);                  \
            accl[3][1] = dp4a_us(aw0[q], wv1.w, accl[3][1]);                  \
            accl[0][2] = dp4a_us(aw1[q], wv0.x, accl[0][2]);                  \
            accl[0][3] = dp4a_us(aw1[q], wv0.y, accl[0][3]);                  \
            accl[1][2] = dp4a_us(aw1[q], wv0.z, accl[1][2]);                  \
            accl[1][3] = dp4a_us(aw1[q], wv0.w, accl[1][3]);                  \
            accl[2][2] = dp4a_us(aw1[q], wv1.x, accl[2][2]);                  \
            accl[2][3] = dp4a_us(aw1[q], wv1.y, accl[2][3]);                  \
            accl[3][2] = dp4a_us(aw1[q], wv1.z, accl[3][2]);                  \
            accl[3][3] = dp4a_us(aw1[q], wv1.w, accl[3][3]);                  \
        }                                                                     \
    }

__global__ __launch_bounds__(256, 3) void conv_hybrid_kernel(float* __restrict__ out)
{
    extern __shared__ __align__(16) char smem[];
    unsigned sb32 = (unsigned)__cvta_generic_to_shared(smem);

    int tid = threadIdx.x;
    int bz = blockIdx.z;
    int b = bz >> 1;
    int co0 = (bz & 1) * 64;
    int h0 = blockIdx.y * 8, w0 = blockIdx.x * 8;

    // act halo tiles (both convs): 1600 16B chunks; invalid -> zero store
    #pragma unroll
    for (int j = 0; j < 7; j++) {
        int i = tid + j * 256;
        if (i < 1600) {
            int cv = i / 800, r = i % 800;
            int p = r >> 3, c16 = r & 7;
            int pr = p / 10 - 1 + h0, pc = p % 10 - 1 + w0;
            char* dgen = smem + (cv ? ACT_L_OFF : ACT_H_OFF) + p * ROWB + c16 * 16;
            if (pr >= 0 && pr < HH && pc >= 0 && pc < WW) {
                const char* src = (const char*)(cv ? g_al : g_ah)
                                  + ((size_t)((b * HH + pr) * WW + pc)) * 128 + c16 * 16;
                unsigned d = (unsigned)__cvta_generic_to_shared(dgen);
                asm volatile("cp.async.cg.shared.global [%0], [%1], 16;" :: "r"(d), "l"(src));
            } else {
                *(uint4*)dgen = make_uint4(0u, 0u, 0u, 0u);
            }
        }
    }
    stage_weights(smem, 0, 0, co0, tid);
    asm volatile("cp.async.commit_group;" ::: "memory");

    int lane = tid & 31, warp = tid >> 5;
    int wm = warp >> 1;          // 0..3 : 16-pixel group (rows 2wm, 2wm+1)
    int wn = warp & 1;           // 0..1 : 32-co group
    int g = lane >> 2, t = lane & 3;

    // ldmatrix lane roles (A operand)
    int lg = lane & 7;
    int rsel = (lane >> 3) & 1;
    int hi16 = (lane >> 4) & 1;

    int acch[4][4], accl[4][4];  // [nt][e]; e: 0,1 = row pin0 co,co+1; 2,3 = row pin1
    #pragma unroll
    for (int nt = 0; nt < 4; nt++)
        #pragma unroll
        for (int q = 0; q < 4; q++) { acch[nt][q] = 0; accl[nt][q] = 0; }

    const char* s_al = smem + ACT_L_OFF;
    unsigned bRow  = sb32 + WH_OFF + (unsigned)(wn * 32 + lane) * ROWB;
    unsigned blRow = sb32 + BL_OFF + (unsigned)(wn * 32 + lane) * 48;

    #pragma unroll 1
    for (int k9 = 0; k9 < 9; k9++) {
        asm volatile("cp.async.wait_group 0;" ::: "memory");
        __syncthreads();
        int buf = k9 & 1;
        if (k9 < 8) {
            stage_weights(smem, buf ^ 1, k9 + 1, co0, tid);
            asm volatile("cp.async.commit_group;" ::: "memory");
        }
        int kh = k9 / 3, kw = k9 - kh * 3;

        unsigned arow = (unsigned)(((2 * wm + kh) * 10 + lg + kw + 10 * rsel) * ROWB)
                      + (unsigned)(hi16 * 16);
        unsigned aAddr = sb32 + ACT_H_OFF + arow;
        unsigned bAddr = bRow + (unsigned)(buf * WH_BUF);
        int pin0 = (2 * wm + kh) * 10 + g + kw;
        int pin1 = pin0 + 10;
        const char* wlb = smem + WL_OFF + buf * WL_BUF + (wn * 4 + t) * 32;

        // ---- interleaved: each mma group followed by one dp4a segment ----
        #pragma unroll
        for (int chunk = 0; chunk < 4; chunk++) {
            unsigned a[4], bA[4], bB[4];
            ldsm_x4(aAddr + chunk * 32, a);
            ldsm_x4(bAddr + chunk * 32, bA);
            ldsm_x4(bAddr + chunk * 32 + 16, bB);
            #pragma unroll
            for (int nt = 0; nt < 4; nt++)
                mma_u8s8(acch[nt], a, bA[nt], bB[nt]);
            DP4A_SEG(chunk);
        }
        {
            unsigned aL[4], bA[4], bB[4];
            ldsm_x4(sb32 + ACT_L_OFF + arow + 96, aL);
            unsigned blAddr = blRow + (unsigned)(buf * BL_BUF);
            ldsm_x4(blAddr, bA);
            ldsm_x4(blAddr + 16, bB);
            #pragma unroll
            for (int nt = 0; nt < 4; nt++)
                mma_u8s8(accl[nt], aL, bA[nt], bB[nt]);
            DP4A_SEG(4);
            DP4A_SEG(5);
        }
    }

    // epilogue: y = fsh*acc_h + fsl*acc_l -> NCHW fp32
    int p0 = wm * 16 + g;
    int oh0 = h0 + (p0 >> 3), ow = w0 + (p0 & 7);
    int oh1 = oh0 + 1;                               // pin1 row = next image row
    #pragma unroll
    for (int nt = 0; nt < 4; nt++) {
        int cg0 = co0 + wn * 32 + nt * 8 + t * 2;
        float sh0 = g_fsh[cg0],     sl0 = g_fsl[cg0];
        float sh1 = g_fsh[cg0 + 1], sl1 = g_fsl[cg0 + 1];
        out[((b * CC + cg0) * HH + oh0) * WW + ow] =
            sh0 * (float)acch[nt][0] + sl0 * (float)accl[nt][0];
        out[((b * CC + cg0 + 1) * HH + oh0) * WW + ow] =
            sh1 * (float)acch[nt][1] + sl1 * (float)accl[nt][1];
        out[((b * CC + cg0) * HH + oh1) * WW + ow] =
            sh0 * (float)acch[nt][2] + sl0 * (float)accl[nt][2];
        out[((b * CC + cg0 + 1) * HH + oh1) * WW + ow] =
            sh1 * (float)acch[nt][3] + sl1 * (float)accl[nt][3];
    }
}

// ---------------- launch ----------------
extern "C" void kernel_launch(void* const* d_in, const int* in_sizes, int n_in,
                              void* d_out, int out_size)
{
    const float* x      = (const float*)d_in[0];
    const float* w_high = (const float*)d_in[1];
    const float* w_low  = (const float*)d_in[2];
    const float* as_h   = (const float*)d_in[3];
    const float* as_l   = (const float*)d_in[4];
    float* out = (float*)d_out;

    cudaFuncSetAttribute(conv_hybrid_kernel,
                         cudaFuncAttributeMaxDynamicSharedMemorySize, CONV_SMEM);

    quant_weights_kernel<<<2 * CC, 256>>>(w_high, w_low, as_h, as_l);
    mask_quant_kernel<<<dim3(WW / 8, HH / 8, BB), 256>>>(x, as_h, as_l);
    conv_hybrid_kernel<<<dim3(WW / 8, HH / 8, BB * 2), 256, CONV_SMEM>>>(out);
}